// round 9
// baseline (speedup 1.0000x reference)
#include <cuda_runtime.h>

// ---------------------------------------------------------------------------
// Compile-time rotation table, bit-exact vs the reference (rel_err 0.0 in
// R4/R6/R7). Trig constants are the correctly-rounded libm doubles of
// cos/sin(k*pi_d/4); their 1-ulp asymmetries decide the cancellation-residue
// sign on diagonal positions and hence round(15.5 -/+ eps). Expression shape
// matches Python exactly: fl(fl(ct*x) - fl(st*y)).
// ---------------------------------------------------------------------------
struct Table { int v[1024]; };

constexpr int iround(double v) {
    // == rint here: only exact .5 reachable is 15.5; +0.5 -> 16 = half-even.
    return v >= 0.0 ? (int)(v + 0.5) : -(int)(0.5 - v);
}
constexpr int iclamp31(int v) { return v < 0 ? 0 : (v > 31 ? 31 : v); }

constexpr Table make_table() {
    Table t{};
    for (int c = 0; c < 1024; c++) t.v[c] = -1;
    const double ct[8] = { 1.0,                     0.7071067811865476,
                           6.123233995736766e-17,  -0.7071067811865475,
                          -1.0,                    -0.7071067811865477,
                          -1.8369701987210297e-16,  0.7071067811865474 };
    const double st[8] = { 0.0,                     0.7071067811865475,
                           1.0,                     0.7071067811865476,
                           1.2246467991473532e-16, -0.7071067811865475,
                          -1.0,                    -0.7071067811865477 };
    int idx = 0;
    for (int i = 0; i < 16; i++) {
        for (int j = 31 - i; j < 32; j++) {       // octant: angle in [0, pi/4]
            double y = 15.5 - (double)i;
            double x = (double)j - 15.5;
            for (int k = 0; k < 8; k++) {
                double xn = ct[k] * x - st[k] * y;
                double yn = st[k] * x + ct[k] * y;
                int ir = iclamp31(iround(15.5 - yn));
                int jr = iclamp31(iround(15.5 + xn));
                t.v[ir * 32 + jr] = idx * 8 + k;   // last write wins
            }
            idx++;
        }
    }
    return t;
}

__constant__ constexpr Table TBL = make_table();

// ---------------------------------------------------------------------------
// Fused gather + broadcast-add. 2D grid: blockIdx.x = token (0..1024),
// blockIdx.y = batch-chunk (0..15). Each thread owns one float4 channel slot
// of its token and streams CHUNK=8 batches: out = x + f.
// x is read-once -> __ldlu (last-use) keeps its lines from lingering in L2;
// out is write-once -> __stcs (evict-first). Occupancy supplies the MLP
// (R4/R5: per-thread batching raises regs, cuts occupancy, lowers DRAM).
// All offsets 32-bit (33.6M float4 < 2^32).
// ---------------------------------------------------------------------------
#define P4      262400u            // float4 per batch row (1025*256)
#define CHUNK   8u                 // batches per block-row

__global__ void __launch_bounds__(256) add_posembed_kernel(
    const float4* __restrict__ x,
    const float4* __restrict__ P,     // (136, 8, 128) f32 = 136*256 float4
    const float4* __restrict__ cls,   // 128 f32 = 32 float4
    float4* __restrict__ out)
{
    const int t  = blockIdx.x;          // token 0..1024 (block-uniform)
    const int c4 = threadIdx.x;         // float4 index within 1024 channels

    float4 f;
    if (t == 0) {
        f = cls[c4 & 31];               // CLS tiled across 8 groups
    } else {
        const int packed = TBL.v[t - 1];
        if (packed < 0) {
            f = make_float4(0.f, 0.f, 0.f, 0.f);
        } else {
            const int group = ((c4 >> 5) - (packed & 7)) & 7;
            f = P[(packed >> 3) * 256 + group * 32 + (c4 & 31)];
        }
    }

    unsigned off = blockIdx.y * (CHUNK * P4) + (unsigned)t * 256u + (unsigned)c4;
#pragma unroll
    for (unsigned b = 0; b < CHUNK; b++) {
        float4 v = __ldlu(x + off);     // last-use: dead-on-read in L2
        v.x += f.x; v.y += f.y; v.z += f.z; v.w += f.w;
        __stcs(out + off, v);
        off += P4;
    }
}

extern "C" void kernel_launch(void* const* d_in, const int* in_sizes, int n_in,
                              void* d_out, int out_size) {
    const float4* x   = (const float4*)d_in[0];  // (128, 1025, 1024) f32
    const float4* P   = (const float4*)d_in[1];  // (1, 136, 1024) f32
    const float4* cls = (const float4*)d_in[2];  // (1, 1, 128) f32
    float4* out = (float4*)d_out;

    dim3 grid(1025, 16);                // 16 chunks x 8 batches = 128
    add_posembed_kernel<<<grid, 256>>>(x, P, cls, out);
}

// round 10
// speedup vs baseline: 1.0134x; 1.0134x over previous
#include <cuda_runtime.h>

// ---------------------------------------------------------------------------
// Compile-time rotation table, bit-exact vs the reference (rel_err 0.0 in
// R4/R6/R7/R9). Trig constants are the correctly-rounded libm doubles of
// cos/sin(k*pi_d/4); their 1-ulp asymmetries decide the cancellation-residue
// sign on diagonal positions and hence round(15.5 -/+ eps). Expression shape
// matches Python exactly: fl(fl(ct*x) - fl(st*y)).
// ---------------------------------------------------------------------------
struct Table { int v[1024]; };

constexpr int iround(double v) {
    // == rint here: only exact .5 reachable is 15.5; +0.5 -> 16 = half-even.
    return v >= 0.0 ? (int)(v + 0.5) : -(int)(0.5 - v);
}
constexpr int iclamp31(int v) { return v < 0 ? 0 : (v > 31 ? 31 : v); }

constexpr Table make_table() {
    Table t{};
    for (int c = 0; c < 1024; c++) t.v[c] = -1;
    const double ct[8] = { 1.0,                     0.7071067811865476,
                           6.123233995736766e-17,  -0.7071067811865475,
                          -1.0,                    -0.7071067811865477,
                          -1.8369701987210297e-16,  0.7071067811865474 };
    const double st[8] = { 0.0,                     0.7071067811865475,
                           1.0,                     0.7071067811865476,
                           1.2246467991473532e-16, -0.7071067811865475,
                          -1.0,                    -0.7071067811865477 };
    int idx = 0;
    for (int i = 0; i < 16; i++) {
        for (int j = 31 - i; j < 32; j++) {       // octant: angle in [0, pi/4]
            double y = 15.5 - (double)i;
            double x = (double)j - 15.5;
            for (int k = 0; k < 8; k++) {
                double xn = ct[k] * x - st[k] * y;
                double yn = st[k] * x + ct[k] * y;
                int ir = iclamp31(iround(15.5 - yn));
                int jr = iclamp31(iround(15.5 + xn));
                t.v[ir * 32 + jr] = idx * 8 + k;   // last write wins
            }
            idx++;
        }
    }
    return t;
}

__constant__ constexpr Table TBL = make_table();

// ---------------------------------------------------------------------------
// Fused gather + broadcast-add. 2D grid: blockIdx.x = token (0..1024),
// blockIdx.y = batch-chunk (0..31). Each thread owns one float4 channel slot
// of its token and streams CHUNK=4 batches: out = x + f.
// Granularity series: 1025 blocks -> DRAM 80.8%, 16400 -> 84.4%; this round
// pushes to 32800 blocks (finer tail smoothing, steadier HBM pressure).
// P/cls re-gathers are L2 hits (P = 139 KB resident). __ldcs/__stcs streaming
// hints (R9 showed __ldlu neutral). Occupancy supplies the MLP (R4/R5:
// per-thread batching regresses). All offsets 32-bit (33.6M float4 < 2^32).
// ---------------------------------------------------------------------------
#define P4      262400u            // float4 per batch row (1025*256)
#define CHUNK   4u                 // batches per block
#define NCHUNK  32u                // 128 / CHUNK

__global__ void __launch_bounds__(256) add_posembed_kernel(
    const float4* __restrict__ x,
    const float4* __restrict__ P,     // (136, 8, 128) f32 = 136*256 float4
    const float4* __restrict__ cls,   // 128 f32 = 32 float4
    float4* __restrict__ out)
{
    const int t  = blockIdx.x;          // token 0..1024 (block-uniform)
    const int c4 = threadIdx.x;         // float4 index within 1024 channels

    float4 f;
    if (t == 0) {
        f = cls[c4 & 31];               // CLS tiled across 8 groups
    } else {
        const int packed = TBL.v[t - 1];
        if (packed < 0) {
            f = make_float4(0.f, 0.f, 0.f, 0.f);
        } else {
            const int group = ((c4 >> 5) - (packed & 7)) & 7;
            f = P[(packed >> 3) * 256 + group * 32 + (c4 & 31)];
        }
    }

    unsigned off = blockIdx.y * (CHUNK * P4) + (unsigned)t * 256u + (unsigned)c4;
#pragma unroll
    for (unsigned b = 0; b < CHUNK; b++) {
        float4 v = __ldcs(x + off);
        v.x += f.x; v.y += f.y; v.z += f.z; v.w += f.w;
        __stcs(out + off, v);
        off += P4;
    }
}

extern "C" void kernel_launch(void* const* d_in, const int* in_sizes, int n_in,
                              void* d_out, int out_size) {
    const float4* x   = (const float4*)d_in[0];  // (128, 1025, 1024) f32
    const float4* P   = (const float4*)d_in[1];  // (1, 136, 1024) f32
    const float4* cls = (const float4*)d_in[2];  // (1, 1, 128) f32
    float4* out = (float4*)d_out;

    dim3 grid(1025, NCHUNK);            // 32 chunks x 4 batches = 128
    add_posembed_kernel<<<grid, 256>>>(x, P, cls, out);
}